// round 7
// baseline (speedup 1.0000x reference)
#include <cuda_runtime.h>
#include <cstdint>

// LengthRegulator, fixed shapes: B=32, T=512, D=384, ML=4096.
//   K1 (precompute, 32 blocks): cumsum + searchsorted -> g_tokpack, mel_pos.
//   K2 (scatter, 8192 blocks): TMA bulk gather (gmem->smem) + TMA bulk store
//      (smem->gmem); LSU only touches the zero tail of invalid frames.
// d_out layout: [B*ML*D floats (out)] then [B*ML floats (mel_pos as float)]

#define B_FIXED 32
#define T_FIXED 512
#define D_FIXED 384
#define ML_FIXED 4096
#define FPB 16                     // frames per scatter block
#define ROW_BYTES (D_FIXED * 4)    // 1536 B per frame row
#define QV 96                      // float4 per frame
#define TPB 128

__device__ int g_tokpack[B_FIXED * ML_FIXED];   // tok | (valid<<16)

// ---------------- K1: precompute ----------------
__global__ void __launch_bounds__(T_FIXED)
lr_precompute(const int* __restrict__ dur, float* __restrict__ melpos)
{
    __shared__ int cum[T_FIXED];
    __shared__ int woff[16];

    const int b = blockIdx.x;
    const int t = threadIdx.x;
    const int lane = t & 31;
    const int w = t >> 5;

    int d = dur[b * T_FIXED + t];
    int v = d;
    #pragma unroll
    for (int off = 1; off < 32; off <<= 1) {
        int n = __shfl_up_sync(0xFFFFFFFFu, v, off);
        if (lane >= off) v += n;
    }
    if (lane == 31) woff[w] = v;
    __syncthreads();
    if (t < 16) {
        int wv = woff[t];
        #pragma unroll
        for (int off = 1; off < 16; off <<= 1) {
            int n = __shfl_up_sync(0x0000FFFFu, wv, off);
            if (t >= off) wv += n;
        }
        woff[t] = wv - woff[t];
    }
    __syncthreads();
    cum[t] = v + woff[w];
    __syncthreads();

    const int total = cum[T_FIXED - 1];

    #pragma unroll
    for (int j = 0; j < ML_FIXED / T_FIXED; ++j) {
        const int f = j * T_FIXED + t;
        int lo = 0, hi = T_FIXED;
        #pragma unroll
        for (int step = 0; step < 10; ++step) {      // interval must reach 0
            if (lo < hi) {
                int mid = (lo + hi) >> 1;
                if (cum[mid] <= f) lo = mid + 1; else hi = mid;
            }
        }
        int tok   = (lo < T_FIXED - 1) ? lo : (T_FIXED - 1);
        int valid = (f < total);
        g_tokpack[b * ML_FIXED + f] = tok | (valid << 16);
        melpos[(size_t)b * ML_FIXED + f] = valid ? (float)(f + 1) : 0.0f;
    }
}

// ---------------- K2: TMA bulk scatter ----------------
__global__ void __launch_bounds__(TPB)
lr_scatter(const float* __restrict__ x, float* __restrict__ out)
{
    __shared__ __align__(128) float4 tile[FPB * QV];   // 24 KB
    __shared__ __align__(8) unsigned long long mbar;
    __shared__ int s_tok[FPB];
    __shared__ int s_nvalid;

    const int b  = blockIdx.y;
    const int f0 = blockIdx.x * FPB;
    const int t  = threadIdx.x;

    uint32_t smem_mbar, smem_tile;
    {
        uint64_t a;
        asm("cvta.to.shared.u64 %0, %1;" : "=l"(a) : "l"((const void*)&mbar));
        smem_mbar = (uint32_t)a;
        asm("cvta.to.shared.u64 %0, %1;" : "=l"(a) : "l"((const void*)tile));
        smem_tile = (uint32_t)a;
    }

    // warp 0: read tok/valid for the block's frames; valid frames are a prefix.
    if (t < 32) {
        int tp = (t < FPB) ? g_tokpack[b * ML_FIXED + f0 + t] : 0;
        if (t < FPB) s_tok[t] = tp & 0xFFFF;
        unsigned m = __ballot_sync(0xFFFFFFFFu, (t < FPB) && (tp >> 16));
        if (t == 0) {
            s_nvalid = __popc(m);
            asm volatile("mbarrier.init.shared.b64 [%0], 1;" :: "r"(smem_mbar) : "memory");
        }
    }
    __syncthreads();

    const int nv = s_nvalid;

    // thread 0: issue TMA bulk loads for valid frames (gmem -> smem)
    if (t == 0 && nv > 0) {
        asm volatile("mbarrier.arrive.expect_tx.shared.b64 _, [%0], %1;"
                     :: "r"(smem_mbar), "r"((uint32_t)(nv * ROW_BYTES)) : "memory");
        const char* xbase = (const char*)(x + (size_t)b * T_FIXED * D_FIXED);
        for (int fr = 0; fr < nv; ++fr) {
            const char* src = xbase + (size_t)s_tok[fr] * ROW_BYTES;
            asm volatile(
                "cp.async.bulk.shared::cta.global.mbarrier::complete_tx::bytes "
                "[%0], [%1], %2, [%3];"
                :: "r"(smem_tile + fr * ROW_BYTES), "l"(src),
                   "r"((uint32_t)ROW_BYTES), "r"(smem_mbar) : "memory");
        }
    }

    // all threads: zero the invalid tail of the tile (STS.128)
    const float4 zero = make_float4(0.f, 0.f, 0.f, 0.f);
    for (int i = nv * QV + t; i < FPB * QV; i += TPB)
        tile[i] = zero;

    // thread 0: wait for all TMA loads
    if (t == 0 && nv > 0) {
        uint32_t done;
        asm volatile(
            "{\n\t.reg .pred p;\n\t"
            "mbarrier.try_wait.parity.shared.b64 p, [%1], 0;\n\t"
            "selp.b32 %0, 1, 0, p;\n\t}"
            : "=r"(done) : "r"(smem_mbar) : "memory");
        while (!done) {
            asm volatile(
                "{\n\t.reg .pred p;\n\t"
                "mbarrier.try_wait.parity.shared.b64 p, [%1], 0, 0x989680;\n\t"
                "selp.b32 %0, 1, 0, p;\n\t}"
                : "=r"(done) : "r"(smem_mbar) : "memory");
        }
    }
    __syncthreads();

    // order generic STS zeros before async-proxy read of smem
    asm volatile("fence.proxy.async.shared::cta;" ::: "memory");

    // thread 0: one bulk store of the whole tile (smem -> gmem)
    if (t == 0) {
        char* dst = (char*)(out + ((size_t)b * ML_FIXED + f0) * D_FIXED);
        asm volatile(
            "cp.async.bulk.global.shared::cta.bulk_group [%0], [%1], %2;"
            :: "l"(dst), "r"(smem_tile), "r"((uint32_t)(FPB * ROW_BYTES)) : "memory");
        asm volatile("cp.async.bulk.commit_group;" ::: "memory");
        asm volatile("cp.async.bulk.wait_group 0;" ::: "memory");   // smem safe to reuse
    }
}

extern "C" void kernel_launch(void* const* d_in, const int* in_sizes, int n_in,
                              void* d_out, int out_size)
{
    const float* x   = (const float*)d_in[0];
    const int*   dur = (const int*)d_in[1];

    float* out    = (float*)d_out;
    float* melpos = out + (size_t)B_FIXED * ML_FIXED * D_FIXED;

    lr_precompute<<<B_FIXED, T_FIXED>>>(dur, melpos);
    dim3 grid(ML_FIXED / FPB, B_FIXED);
    lr_scatter<<<grid, TPB>>>(x, out);
}

// round 8
// speedup vs baseline: 1.1641x; 1.1641x over previous
#include <cuda_runtime.h>
#include <cstdint>

// LengthRegulator, fixed shapes: B=32, T=512, D=384, ML=4096.
//   K1 (precompute, 32 blocks): cumsum + searchsorted -> g_tokpack, mel_pos.
//   K2 (scatter, 8192 blocks, FPB=16): dedup distinct x rows per block,
//      cp.async.cg them into smem ONCE, replicate to output via LDS+STG.cs.
//      Cuts L2 gather-read amplification ~3x (monotone tok, avg dur 3.5).
// d_out layout: [B*ML*D floats (out)] then [B*ML floats (mel_pos as float)]

#define B_FIXED 32
#define T_FIXED 512
#define D_FIXED 384
#define ML_FIXED 4096
#define FPB 16
#define QV 96                      // float4 per frame row
#define TPB 256

__device__ int g_tokpack[B_FIXED * ML_FIXED];   // tok | (valid<<16)

// ---------------- K1: precompute ----------------
__global__ void __launch_bounds__(T_FIXED)
lr_precompute(const int* __restrict__ dur, float* __restrict__ melpos)
{
    __shared__ int cum[T_FIXED];
    __shared__ int woff[16];

    const int b = blockIdx.x;
    const int t = threadIdx.x;
    const int lane = t & 31;
    const int w = t >> 5;

    int d = dur[b * T_FIXED + t];
    int v = d;
    #pragma unroll
    for (int off = 1; off < 32; off <<= 1) {
        int n = __shfl_up_sync(0xFFFFFFFFu, v, off);
        if (lane >= off) v += n;
    }
    if (lane == 31) woff[w] = v;
    __syncthreads();
    if (t < 16) {
        int wv = woff[t];
        #pragma unroll
        for (int off = 1; off < 16; off <<= 1) {
            int n = __shfl_up_sync(0x0000FFFFu, wv, off);
            if (t >= off) wv += n;
        }
        woff[t] = wv - woff[t];
    }
    __syncthreads();
    cum[t] = v + woff[w];
    __syncthreads();

    const int total = cum[T_FIXED - 1];

    #pragma unroll
    for (int j = 0; j < ML_FIXED / T_FIXED; ++j) {
        const int f = j * T_FIXED + t;
        int lo = 0, hi = T_FIXED;
        #pragma unroll
        for (int step = 0; step < 10; ++step) {      // interval must reach 0
            if (lo < hi) {
                int mid = (lo + hi) >> 1;
                if (cum[mid] <= f) lo = mid + 1; else hi = mid;
            }
        }
        int tok   = (lo < T_FIXED - 1) ? lo : (T_FIXED - 1);
        int valid = (f < total);
        g_tokpack[b * ML_FIXED + f] = tok | (valid << 16);
        melpos[(size_t)b * ML_FIXED + f] = valid ? (float)(f + 1) : 0.0f;
    }
}

// ---------------- K2: dedup gather + replicate scatter ----------------
__global__ void __launch_bounds__(TPB)
lr_scatter(const float* __restrict__ x, float* __restrict__ out)
{
    __shared__ __align__(16) float4 tile[FPB * QV];  // 24 KB (worst: all distinct)
    __shared__ int s_uniq[FPB];                      // distinct token ids
    __shared__ int s_slotv[FPB];                     // slot | (valid<<16)
    __shared__ int s_n;                              // number of distinct rows

    const int b  = blockIdx.y;
    const int f0 = blockIdx.x * FPB;
    const int t  = threadIdx.x;

    // warp 0: dedup map. valid frames are a prefix; tok is monotone.
    if (t < 32) {
        int tp = (t < FPB) ? g_tokpack[b * ML_FIXED + f0 + t] : 0;
        int tok   = tp & 0xFFFF;
        int valid = tp >> 16;
        int ptok  = __shfl_up_sync(0xFFFFFFFFu, tok, 1);
        bool isnew = valid && ((t == 0) || tok != ptok);
        unsigned m = __ballot_sync(0xFFFFFFFFu, isnew);
        // slot = (# news at positions <= t) - 1 : index of this frame's row
        int slot = __popc(m & ((2u << t) - 1u)) - 1;
        if (isnew) s_uniq[slot] = tok;
        if (t < FPB) s_slotv[t] = (slot & 0xFFFF) | (valid << 16);
        if (t == 0) s_n = __popc(m);
    }
    __syncthreads();

    const int nUniq = s_n;

    // cooperative load of distinct rows: cp.async.cg (L2-direct), 16B/thread
    {
        const float4* __restrict__ x4 = (const float4*)(x + (size_t)b * T_FIXED * D_FIXED);
        for (int i = t; i < nUniq * QV; i += TPB) {
            int r = i / QV;
            int q = i - r * QV;
            const float4* src = &x4[(size_t)s_uniq[r] * QV + q];
            uint32_t dst = (uint32_t)__cvta_generic_to_shared(&tile[i]);
            asm volatile("cp.async.cg.shared.global [%0], [%1], 16;"
                         :: "r"(dst), "l"(src) : "memory");
        }
        asm volatile("cp.async.commit_group;" ::: "memory");
        asm volatile("cp.async.wait_group 0;" ::: "memory");
    }
    __syncthreads();

    // replicate to output: FPB*QV = 1536 float4, 6 per thread, streaming stores
    float4* __restrict__ o4 = (float4*)(out + ((size_t)b * ML_FIXED + f0) * D_FIXED);
    const float4 zero = make_float4(0.f, 0.f, 0.f, 0.f);

    #pragma unroll
    for (int j = 0; j < (FPB * QV) / TPB; ++j) {
        const int i  = j * TPB + t;
        const int fr = i / QV;
        const int q  = i - fr * QV;
        const int sv = s_slotv[fr];
        float4 val = (sv >> 16) ? tile[(sv & 0xFFFF) * QV + q] : zero;
        __stcs(&o4[(size_t)fr * QV + q], val);
    }
}

extern "C" void kernel_launch(void* const* d_in, const int* in_sizes, int n_in,
                              void* d_out, int out_size)
{
    const float* x   = (const float*)d_in[0];
    const int*   dur = (const int*)d_in[1];

    float* out    = (float*)d_out;
    float* melpos = out + (size_t)B_FIXED * ML_FIXED * D_FIXED;

    lr_precompute<<<B_FIXED, T_FIXED>>>(dur, melpos);
    dim3 grid(ML_FIXED / FPB, B_FIXED);
    lr_scatter<<<grid, TPB>>>(x, out);
}

// round 10
// speedup vs baseline: 1.1650x; 1.0008x over previous
#include <cuda_runtime.h>
#include <cstdint>

// LengthRegulator, fixed shapes: B=32, T=512, D=384, ML=4096.
//   K1 (precompute, 32 blocks): cumsum + searchsorted -> g_tokpack only.
//   K2 (scatter, 8192 blocks, FPB=16, PDL): dedup distinct x rows per block,
//      cp.async.cg into smem once, replicate via LDS+STG.cs; writes mel_pos.
//   K2 launched with programmatic stream serialization: blocks start during
//   K1 and gate on cudaGridDependencySynchronize() before reading g_tokpack.
// d_out layout: [B*ML*D floats (out)] then [B*ML floats (mel_pos as float)]

#define B_FIXED 32
#define T_FIXED 512
#define D_FIXED 384
#define ML_FIXED 4096
#define FPB 16
#define QV 96                      // float4 per frame row
#define TPB 256

__device__ int g_tokpack[B_FIXED * ML_FIXED];   // tok | (valid<<16)

// ---------------- K1: precompute (tokpack only) ----------------
__global__ void __launch_bounds__(T_FIXED)
lr_precompute(const int* __restrict__ dur)
{
    __shared__ int cum[T_FIXED];
    __shared__ int woff[16];

    const int b = blockIdx.x;
    const int t = threadIdx.x;
    const int lane = t & 31;
    const int w = t >> 5;

    int d = dur[b * T_FIXED + t];
    int v = d;
    #pragma unroll
    for (int off = 1; off < 32; off <<= 1) {
        int n = __shfl_up_sync(0xFFFFFFFFu, v, off);
        if (lane >= off) v += n;
    }
    if (lane == 31) woff[w] = v;
    __syncthreads();
    if (t < 16) {
        int wv = woff[t];
        #pragma unroll
        for (int off = 1; off < 16; off <<= 1) {
            int n = __shfl_up_sync(0x0000FFFFu, wv, off);
            if (t >= off) wv += n;
        }
        woff[t] = wv - woff[t];
    }
    __syncthreads();
    cum[t] = v + woff[w];
    __syncthreads();

    const int total = cum[T_FIXED - 1];

    #pragma unroll
    for (int j = 0; j < ML_FIXED / T_FIXED; ++j) {
        const int f = j * T_FIXED + t;
        int lo = 0, hi = T_FIXED;
        #pragma unroll
        for (int step = 0; step < 10; ++step) {      // interval must reach 0
            if (lo < hi) {
                int mid = (lo + hi) >> 1;
                if (cum[mid] <= f) lo = mid + 1; else hi = mid;
            }
        }
        int tok   = (lo < T_FIXED - 1) ? lo : (T_FIXED - 1);
        int valid = (f < total);
        g_tokpack[b * ML_FIXED + f] = tok | (valid << 16);
    }

#if __CUDA_ARCH__ >= 900
    cudaTriggerProgrammaticLaunchCompletion();
#endif
}

// ---------------- K2: dedup gather + replicate scatter (PDL consumer) ------
__global__ void __launch_bounds__(TPB)
lr_scatter(const float* __restrict__ x, float* __restrict__ out,
           float* __restrict__ melpos)
{
    __shared__ __align__(16) float4 tile[FPB * QV];  // 24 KB (worst: all distinct)
    __shared__ int s_uniq[FPB];                      // distinct token ids
    __shared__ int s_slotv[FPB];                     // slot | (valid<<16)
    __shared__ int s_n;                              // number of distinct rows

    const int b  = blockIdx.y;
    const int f0 = blockIdx.x * FPB;
    const int t  = threadIdx.x;

    // Pre-sync (independent of K1): address math only.
    const float4* __restrict__ x4 = (const float4*)(x + (size_t)b * T_FIXED * D_FIXED);
    float4* __restrict__ o4 = (float4*)(out + ((size_t)b * ML_FIXED + f0) * D_FIXED);

#if __CUDA_ARCH__ >= 900
    cudaGridDependencySynchronize();     // wait for K1's g_tokpack writes
#endif

    // warp 0: dedup map. valid frames are a prefix; tok is monotone.
    if (t < 32) {
        int tp = (t < FPB) ? g_tokpack[b * ML_FIXED + f0 + t] : 0;
        int tok   = tp & 0xFFFF;
        int valid = tp >> 16;
        int ptok  = __shfl_up_sync(0xFFFFFFFFu, tok, 1);
        bool isnew = valid && ((t == 0) || tok != ptok);
        unsigned m = __ballot_sync(0xFFFFFFFFu, isnew);
        int slot = __popc(m & ((2u << t) - 1u)) - 1;   // row slot for this frame
        if (isnew) s_uniq[slot] = tok;
        if (t < FPB) s_slotv[t] = (slot & 0xFFFF) | (valid << 16);
        if (t == 0) s_n = __popc(m);
        if (t < FPB)
            melpos[(size_t)b * ML_FIXED + f0 + t] = valid ? (float)(f0 + t + 1) : 0.0f;
    }
    __syncthreads();

    const int nUniq = s_n;

    // cooperative load of distinct rows: cp.async.cg (L2-direct), 16B/thread
    for (int i = t; i < nUniq * QV; i += TPB) {
        int r = i / QV;
        int q = i - r * QV;
        const float4* src = &x4[(size_t)s_uniq[r] * QV + q];
        uint32_t dst = (uint32_t)__cvta_generic_to_shared(&tile[i]);
        asm volatile("cp.async.cg.shared.global [%0], [%1], 16;"
                     :: "r"(dst), "l"(src) : "memory");
    }
    asm volatile("cp.async.commit_group;" ::: "memory");
    asm volatile("cp.async.wait_group 0;" ::: "memory");
    __syncthreads();

    // replicate to output: FPB*QV = 1536 float4, 6 per thread, streaming stores
    const float4 zero = make_float4(0.f, 0.f, 0.f, 0.f);
    #pragma unroll
    for (int j = 0; j < (FPB * QV) / TPB; ++j) {
        const int i  = j * TPB + t;
        const int fr = i / QV;
        const int q  = i - fr * QV;
        const int sv = s_slotv[fr];
        float4 val = (sv >> 16) ? tile[(sv & 0xFFFF) * QV + q] : zero;
        __stcs(&o4[(size_t)fr * QV + q], val);
    }
}

extern "C" void kernel_launch(void* const* d_in, const int* in_sizes, int n_in,
                              void* d_out, int out_size)
{
    const float* x   = (const float*)d_in[0];
    const int*   dur = (const int*)d_in[1];

    float* out    = (float*)d_out;
    float* melpos = out + (size_t)B_FIXED * ML_FIXED * D_FIXED;

    lr_precompute<<<B_FIXED, T_FIXED>>>(dur);

    // PDL launch: scatter blocks may start during K1; they gate internally.
    cudaLaunchConfig_t cfg = {};
    cfg.gridDim  = dim3(ML_FIXED / FPB, B_FIXED);
    cfg.blockDim = dim3(TPB);
    cfg.dynamicSmemBytes = 0;
    cfg.stream = 0;
    cudaLaunchAttribute attr[1];
    attr[0].id = cudaLaunchAttributeProgrammaticStreamSerialization;
    attr[0].val.programmaticStreamSerializationAllowed = 1;
    cfg.attrs = attr;
    cfg.numAttrs = 1;
    cudaLaunchKernelEx(&cfg, lr_scatter, x, out, melpos);
}

// round 14
// speedup vs baseline: 1.2149x; 1.0428x over previous
#include <cuda_runtime.h>
#include <cstdint>

// LengthRegulator, fixed shapes: B=32, T=512, D=384, ML=4096.
//   K1 (precompute, 32 blocks): cumsum + searchsorted -> g_tokpack + mel_pos
//      (coalesced), then triggers programmatic launch completion.
//   K2 (scatter, 8192 blocks, FPB=16, PDL): gates on K1, dedups distinct x
//      rows per block, cp.async.cg into smem once, replicates via LDS+STG.cs.
// d_out layout: [B*ML*D floats (out)] then [B*ML floats (mel_pos as float)]

#define B_FIXED 32
#define T_FIXED 512
#define D_FIXED 384
#define ML_FIXED 4096
#define FPB 16
#define QV 96                      // float4 per frame row
#define TPB 256

__device__ int g_tokpack[B_FIXED * ML_FIXED];   // tok | (valid<<16)

// ---------------- K1: precompute ----------------
__global__ void __launch_bounds__(T_FIXED)
lr_precompute(const int* __restrict__ dur, float* __restrict__ melpos)
{
    __shared__ int cum[T_FIXED];
    __shared__ int woff[16];

    const int b = blockIdx.x;
    const int t = threadIdx.x;
    const int lane = t & 31;
    const int w = t >> 5;

    int d = dur[b * T_FIXED + t];
    int v = d;
    #pragma unroll
    for (int off = 1; off < 32; off <<= 1) {
        int n = __shfl_up_sync(0xFFFFFFFFu, v, off);
        if (lane >= off) v += n;
    }
    if (lane == 31) woff[w] = v;
    __syncthreads();
    if (t < 16) {
        int wv = woff[t];
        #pragma unroll
        for (int off = 1; off < 16; off <<= 1) {
            int n = __shfl_up_sync(0x0000FFFFu, wv, off);
            if (t >= off) wv += n;
        }
        woff[t] = wv - woff[t];
    }
    __syncthreads();
    cum[t] = v + woff[w];
    __syncthreads();

    const int total = cum[T_FIXED - 1];

    #pragma unroll
    for (int j = 0; j < ML_FIXED / T_FIXED; ++j) {
        const int f = j * T_FIXED + t;                 // coalesced across t
        int lo = 0, hi = T_FIXED;
        #pragma unroll
        for (int step = 0; step < 10; ++step) {        // interval must reach 0
            if (lo < hi) {
                int mid = (lo + hi) >> 1;
                if (cum[mid] <= f) lo = mid + 1; else hi = mid;
            }
        }
        int tok   = (lo < T_FIXED - 1) ? lo : (T_FIXED - 1);
        int valid = (f < total);
        g_tokpack[b * ML_FIXED + f] = tok | (valid << 16);
        melpos[(size_t)b * ML_FIXED + f] = valid ? (float)(f + 1) : 0.0f;
    }

#if __CUDA_ARCH__ >= 900
    cudaTriggerProgrammaticLaunchCompletion();
#endif
}

// ---------------- K2: dedup gather + replicate scatter (PDL consumer) ------
__global__ void __launch_bounds__(TPB)
lr_scatter(const float* __restrict__ x, float* __restrict__ out)
{
    __shared__ __align__(16) float4 tile[FPB * QV];  // 24 KB (worst: all distinct)
    __shared__ int s_uniq[FPB];                      // distinct token ids
    __shared__ int s_slotv[FPB];                     // slot | (valid<<16)
    __shared__ int s_n;                              // number of distinct rows

    const int b  = blockIdx.y;
    const int f0 = blockIdx.x * FPB;
    const int t  = threadIdx.x;

    const float4* __restrict__ x4 = (const float4*)(x + (size_t)b * T_FIXED * D_FIXED);
    float4* __restrict__ o4 = (float4*)(out + ((size_t)b * ML_FIXED + f0) * D_FIXED);

#if __CUDA_ARCH__ >= 900
    cudaGridDependencySynchronize();     // wait for K1's g_tokpack writes
#endif

    // warp 0: dedup map. valid frames are a prefix; tok is monotone.
    if (t < 32) {
        int tp = (t < FPB) ? g_tokpack[b * ML_FIXED + f0 + t] : 0;
        int tok   = tp & 0xFFFF;
        int valid = tp >> 16;
        int ptok  = __shfl_up_sync(0xFFFFFFFFu, tok, 1);
        bool isnew = valid && ((t == 0) || tok != ptok);
        unsigned m = __ballot_sync(0xFFFFFFFFu, isnew);
        int slot = __popc(m & ((2u << t) - 1u)) - 1;   // row slot for this frame
        if (isnew) s_uniq[slot] = tok;
        if (t < FPB) s_slotv[t] = (slot & 0xFFFF) | (valid << 16);
        if (t == 0) s_n = __popc(m);
    }
    __syncthreads();

    const int nUniq = s_n;

    // cooperative load of distinct rows: cp.async.cg (L2-direct), 16B/thread
    for (int i = t; i < nUniq * QV; i += TPB) {
        int r = i / QV;
        int q = i - r * QV;
        const float4* src = &x4[(size_t)s_uniq[r] * QV + q];
        uint32_t dst = (uint32_t)__cvta_generic_to_shared(&tile[i]);
        asm volatile("cp.async.cg.shared.global [%0], [%1], 16;"
                     :: "r"(dst), "l"(src) : "memory");
    }
    asm volatile("cp.async.commit_group;" ::: "memory");
    asm volatile("cp.async.wait_group 0;" ::: "memory");
    __syncthreads();

    // replicate to output: FPB*QV = 1536 float4, 6 per thread, streaming stores
    const float4 zero = make_float4(0.f, 0.f, 0.f, 0.f);
    #pragma unroll
    for (int j = 0; j < (FPB * QV) / TPB; ++j) {
        const int i  = j * TPB + t;
        const int fr = i / QV;
        const int q  = i - fr * QV;
        const int sv = s_slotv[fr];
        float4 val = (sv >> 16) ? tile[(sv & 0xFFFF) * QV + q] : zero;
        __stcs(&o4[(size_t)fr * QV + q], val);
    }
}

extern "C" void kernel_launch(void* const* d_in, const int* in_sizes, int n_in,
                              void* d_out, int out_size)
{
    const float* x   = (const float*)d_in[0];
    const int*   dur = (const int*)d_in[1];

    float* out    = (float*)d_out;
    float* melpos = out + (size_t)B_FIXED * ML_FIXED * D_FIXED;

    lr_precompute<<<B_FIXED, T_FIXED>>>(dur, melpos);

    // PDL launch: scatter blocks may start during K1; they gate internally.
    cudaLaunchConfig_t cfg = {};
    cfg.gridDim  = dim3(ML_FIXED / FPB, B_FIXED);
    cfg.blockDim = dim3(TPB);
    cfg.dynamicSmemBytes = 0;
    cfg.stream = 0;
    cudaLaunchAttribute attr[1];
    attr[0].id = cudaLaunchAttributeProgrammaticStreamSerialization;
    attr[0].val.programmaticStreamSerializationAllowed = 1;
    cfg.attrs = attr;
    cfg.numAttrs = 1;
    cudaLaunchKernelEx(&cfg, lr_scatter, x, out);
}

// round 15
// speedup vs baseline: 1.2339x; 1.0157x over previous
#include <cuda_runtime.h>
#include <cstdint>

// LengthRegulator, fixed shapes: B=32, T=512, D=384, ML=4096.
//   K1 (precompute, grid(32,4)): each sub-block redoes its batch's cumsum
//      (cheap) and covers 1024 frames (2 searches/thread) -> tokpack + mel_pos.
//      Parallelized so the PDL trigger fires ~2x earlier.
//   K2 (scatter, 8192 blocks, FPB=16, PDL): gates on K1, dedups distinct x
//      rows per block, cp.async.cg into smem once, replicates via LDS+STG.cs.
//      At the HBM write wall (~201MB stores, ~7 TB/s combined traffic).
// d_out layout: [B*ML*D floats (out)] then [B*ML floats (mel_pos as float)]

#define B_FIXED 32
#define T_FIXED 512
#define D_FIXED 384
#define ML_FIXED 4096
#define FPB 16
#define QV 96                      // float4 per frame row
#define TPB 256
#define K1_SPLIT 4                 // sub-blocks per batch in K1
#define K1_FR (ML_FIXED / K1_SPLIT / T_FIXED)   // frames per thread = 2

__device__ int g_tokpack[B_FIXED * ML_FIXED];   // tok | (valid<<16)

// ---------------- K1: precompute ----------------
__global__ void __launch_bounds__(T_FIXED)
lr_precompute(const int* __restrict__ dur, float* __restrict__ melpos)
{
    __shared__ int cum[T_FIXED];
    __shared__ int woff[16];

    const int b  = blockIdx.x;
    const int sb = blockIdx.y;               // sub-block: frame range owner
    const int t  = threadIdx.x;
    const int lane = t & 31;
    const int w = t >> 5;

    int d = dur[b * T_FIXED + t];
    int v = d;
    #pragma unroll
    for (int off = 1; off < 32; off <<= 1) {
        int n = __shfl_up_sync(0xFFFFFFFFu, v, off);
        if (lane >= off) v += n;
    }
    if (lane == 31) woff[w] = v;
    __syncthreads();
    if (t < 16) {
        int wv = woff[t];
        #pragma unroll
        for (int off = 1; off < 16; off <<= 1) {
            int n = __shfl_up_sync(0x0000FFFFu, wv, off);
            if (t >= off) wv += n;
        }
        woff[t] = wv - woff[t];
    }
    __syncthreads();
    cum[t] = v + woff[w];
    __syncthreads();

    const int total = cum[T_FIXED - 1];
    const int fbase = sb * (ML_FIXED / K1_SPLIT);

    #pragma unroll
    for (int j = 0; j < K1_FR; ++j) {
        const int f = fbase + j * T_FIXED + t;         // coalesced across t
        int lo = 0, hi = T_FIXED;
        #pragma unroll
        for (int step = 0; step < 10; ++step) {        // interval must reach 0
            if (lo < hi) {
                int mid = (lo + hi) >> 1;
                if (cum[mid] <= f) lo = mid + 1; else hi = mid;
            }
        }
        int tok   = (lo < T_FIXED - 1) ? lo : (T_FIXED - 1);
        int valid = (f < total);
        g_tokpack[b * ML_FIXED + f] = tok | (valid << 16);
        melpos[(size_t)b * ML_FIXED + f] = valid ? (float)(f + 1) : 0.0f;
    }

#if __CUDA_ARCH__ >= 900
    cudaTriggerProgrammaticLaunchCompletion();
#endif
}

// ---------------- K2: dedup gather + replicate scatter (PDL consumer) ------
__global__ void __launch_bounds__(TPB)
lr_scatter(const float* __restrict__ x, float* __restrict__ out)
{
    __shared__ __align__(16) float4 tile[FPB * QV];  // 24 KB (worst: all distinct)
    __shared__ int s_uniq[FPB];                      // distinct token ids
    __shared__ int s_slotv[FPB];                     // slot | (valid<<16)
    __shared__ int s_n;                              // number of distinct rows

    const int b  = blockIdx.y;
    const int f0 = blockIdx.x * FPB;
    const int t  = threadIdx.x;

    const float4* __restrict__ x4 = (const float4*)(x + (size_t)b * T_FIXED * D_FIXED);
    float4* __restrict__ o4 = (float4*)(out + ((size_t)b * ML_FIXED + f0) * D_FIXED);

#if __CUDA_ARCH__ >= 900
    cudaGridDependencySynchronize();     // wait for K1's g_tokpack writes
#endif

    // warp 0: dedup map. valid frames are a prefix; tok is monotone.
    if (t < 32) {
        int tp = (t < FPB) ? g_tokpack[b * ML_FIXED + f0 + t] : 0;
        int tok   = tp & 0xFFFF;
        int valid = tp >> 16;
        int ptok  = __shfl_up_sync(0xFFFFFFFFu, tok, 1);
        bool isnew = valid && ((t == 0) || tok != ptok);
        unsigned m = __ballot_sync(0xFFFFFFFFu, isnew);
        int slot = __popc(m & ((2u << t) - 1u)) - 1;   // row slot for this frame
        if (isnew) s_uniq[slot] = tok;
        if (t < FPB) s_slotv[t] = (slot & 0xFFFF) | (valid << 16);
        if (t == 0) s_n = __popc(m);
    }
    __syncthreads();

    const int nUniq = s_n;

    // cooperative load of distinct rows: cp.async.cg (L2-direct), 16B/thread
    for (int i = t; i < nUniq * QV; i += TPB) {
        int r = i / QV;
        int q = i - r * QV;
        const float4* src = &x4[(size_t)s_uniq[r] * QV + q];
        uint32_t dst = (uint32_t)__cvta_generic_to_shared(&tile[i]);
        asm volatile("cp.async.cg.shared.global [%0], [%1], 16;"
                     :: "r"(dst), "l"(src) : "memory");
    }
    asm volatile("cp.async.commit_group;" ::: "memory");
    asm volatile("cp.async.wait_group 0;" ::: "memory");
    __syncthreads();

    // replicate to output: FPB*QV = 1536 float4, 6 per thread, streaming stores
    const float4 zero = make_float4(0.f, 0.f, 0.f, 0.f);
    #pragma unroll
    for (int j = 0; j < (FPB * QV) / TPB; ++j) {
        const int i  = j * TPB + t;
        const int fr = i / QV;
        const int q  = i - fr * QV;
        const int sv = s_slotv[fr];
        float4 val = (sv >> 16) ? tile[(sv & 0xFFFF) * QV + q] : zero;
        __stcs(&o4[(size_t)fr * QV + q], val);
    }
}

extern "C" void kernel_launch(void* const* d_in, const int* in_sizes, int n_in,
                              void* d_out, int out_size)
{
    const float* x   = (const float*)d_in[0];
    const int*   dur = (const int*)d_in[1];

    float* out    = (float*)d_out;
    float* melpos = out + (size_t)B_FIXED * ML_FIXED * D_FIXED;

    lr_precompute<<<dim3(B_FIXED, K1_SPLIT), T_FIXED>>>(dur, melpos);

    // PDL launch: scatter blocks may start during K1; they gate internally.
    cudaLaunchConfig_t cfg = {};
    cfg.gridDim  = dim3(ML_FIXED / FPB, B_FIXED);
    cfg.blockDim = dim3(TPB);
    cfg.dynamicSmemBytes = 0;
    cfg.stream = 0;
    cudaLaunchAttribute attr[1];
    attr[0].id = cudaLaunchAttributeProgrammaticStreamSerialization;
    attr[0].val.programmaticStreamSerializationAllowed = 1;
    cfg.attrs = attr;
    cfg.numAttrs = 1;
    cudaLaunchKernelEx(&cfg, lr_scatter, x, out);
}